// round 14
// baseline (speedup 1.0000x reference)
#include <cuda_runtime.h>
#include <cstdint>

// Fixed problem shapes
static constexpr int NP     = 128;           // partitions
static constexpr int Cc     = 32;            // key channels
static constexpr int Dd     = 128;           // value/query dim
static constexpr int Bb     = 4;
static constexpr int Ss     = 2048;
static constexpr int Kk     = 2;
static constexpr int NPAIRS = Bb * Ss * Kk;  // 16384
static constexpr int NTOK   = Bb * Ss;       // 8192

static constexpr int NTHR   = 1024;
static constexpr int NBLK   = 2 * NP;        // 256 blocks = (partition, half)
static constexpr int HALFN  = NPAIRS / 2;    // 8192 pairs per half
static constexpr int PER    = HALFN / 4 / NTHR;    // 2 int4 per thread
static constexpr int CAP    = 512;           // per-(p,half) capacity (mean 64, sigma 8)

static constexpr int ONTHR  = 256;
static constexpr int ONBLK  = NTOK * Dd / 4 / ONTHR;  // 1024 blocks, 1 f4/thread

// Persistent scratch: per-(half,partition) partial rows. Fully rewritten by
// k_scatter every launch (gather formulation -> no zeroing, no atomics).
__device__ float g_P[2 * NP * Dd];

// ---------------------------------------------------------------------------
// k_scatter: 256 blocks x 1024 threads, 2 CTAs/SM. Block (p,h):
//   Phase 1:  scan half h of idx (2 int4/thread, strided-coalesced),
//             two-level shfl scan -> deterministic compaction (~64 matches).
//   Phase 2:  OVERLAPPED gather — each thread issues its slice's value-row
//             float4 loads (addresses need only js, not w) AND its octet
//             key-row load back-to-back, so the keys and values DRAM
//             episodes fly concurrently; butterfly-shfl finishes w; after
//             one barrier, FMA uses the already-resident value registers.
//             Transpose + warp-shfl reduce -> g_P[h][p] row.
// ---------------------------------------------------------------------------
__global__ void __launch_bounds__(NTHR, 2) k_scatter(
    const int*   __restrict__ idx,
    const float* __restrict__ keys,
    const float* __restrict__ values)
{
    __shared__ int    js[CAP];
    __shared__ float  wls[CAP];
    __shared__ int    wsum[32];
    __shared__ float4 red4[32][33];          // padded transpose buffer

    const int p    = blockIdx.x >> 1;
    const int h    = blockIdx.x & 1;
    const int tid  = threadIdx.x;
    const int lane = tid & 31;
    const int wid  = tid >> 5;

    // ---- Phase 1a: strided-coalesced idx load (2 int4/thread), count
    const int4* idx4 = (const int4*)idx + h * (HALFN / 4);
    int4 my[PER];
    int cnt = 0;
    #pragma unroll
    for (int i = 0; i < PER; i++) {
        my[i] = idx4[i * NTHR + tid];
        cnt += (my[i].x == p) + (my[i].y == p) + (my[i].z == p) + (my[i].w == p);
    }

    // ---- Phase 1b: two-level exclusive scan (warp shfl + 32-entry top)
    int inc = cnt;
    #pragma unroll
    for (int o = 1; o < 32; o <<= 1) {
        int v = __shfl_up_sync(0xFFFFFFFFu, inc, o);
        if (lane >= o) inc += v;
    }
    if (lane == 31) wsum[wid] = inc;
    __syncthreads();
    if (wid == 0) {
        int v = wsum[lane];
        #pragma unroll
        for (int o = 1; o < 32; o <<= 1) {
            int u = __shfl_up_sync(0xFFFFFFFFu, v, o);
            if (lane >= o) v += u;
        }
        wsum[lane] = v;                      // inclusive prefix of warp totals
    }
    __syncthreads();
    int n   = wsum[31];
    int pos = (wid ? wsum[wid - 1] : 0) + (inc - cnt);

    // ---- Phase 1c: emit matched pair indices (fixed deterministic order)
    #pragma unroll
    for (int i = 0; i < PER; i++) {
        const int j = h * HALFN + (i * NTHR + tid) * 4;
        if (my[i].x == p && pos < CAP) js[pos++] = j + 0;
        if (my[i].y == p && pos < CAP) js[pos++] = j + 1;
        if (my[i].z == p && pos < CAP) js[pos++] = j + 2;
        if (my[i].w == p && pos < CAP) js[pos++] = j + 3;
    }
    if (n > CAP) n = CAP;
    __syncthreads();

    // ---- Phase 2: overlapped keys+values gather.
    const int slice = tid >> 5;
    const int d4    = tid & 31;
    const float4* V4 = (const float4*)values;

    // (a) hoisted value-row loads for this thread's first two matches —
    // addresses depend only on js, so these LDGs fly with the key LDGs below.
    const int m0 = slice, m1 = slice + 32;
    float4 v0 = make_float4(0.f, 0.f, 0.f, 0.f);
    float4 v1 = make_float4(0.f, 0.f, 0.f, 0.f);
    if (m0 < n) v0 = V4[(js[m0] >> 1) * 32 + d4];
    if (m1 < n) v1 = V4[(js[m1] >> 1) * 32 + d4];

    // (b) key rows: 8 threads per 128B row, octet butterfly -> wls[m]
    {
        const int lane8 = tid & 7;
        const int row8  = tid >> 3;
        for (int b = 0; b < n; b += NTHR / 8) {   // 1 sweep for n <= 128
            const int m = b + row8;
            float s = 0.f;
            if (m < n) {
                float4 kv = ((const float4*)keys)[(size_t)js[m] * (Cc / 4) + lane8];
                s = (kv.x + kv.y) + (kv.z + kv.w);
            }
            s += __shfl_xor_sync(0xFFFFFFFFu, s, 1);
            s += __shfl_xor_sync(0xFFFFFFFFu, s, 2);
            s += __shfl_xor_sync(0xFFFFFFFFu, s, 4);
            if (m < n && lane8 == 0) wls[m] = s * (1.0f / Cc);
        }
    }
    __syncthreads();

    // (c) FMA with resident value registers (same accumulation order as the
    // old m = slice, slice+32, slice+64, ... loop -> bitwise identical).
    {
        float4 acc = make_float4(0.f, 0.f, 0.f, 0.f);
        if (m0 < n) {
            const float w = wls[m0];
            acc.x += w * v0.x; acc.y += w * v0.y;
            acc.z += w * v0.z; acc.w += w * v0.w;
        }
        if (m1 < n) {
            const float w = wls[m1];
            acc.x += w * v1.x; acc.y += w * v1.y;
            acc.z += w * v1.z; acc.w += w * v1.w;
        }
        for (int m = slice + 64; m < n; m += 32) {   // rare tail (n > 96)
            const float w = wls[m];
            float4 v = V4[(js[m] >> 1) * 32 + d4];
            acc.x += w * v.x; acc.y += w * v.y;
            acc.z += w * v.z; acc.w += w * v.w;
        }
        red4[slice][d4] = acc;
        __syncthreads();
        // warp-transpose reduce: warp `wid` owns column d4=wid, lanes=slices
        float4 v = red4[lane][wid];
        #pragma unroll
        for (int o = 16; o >= 1; o >>= 1) {
            v.x += __shfl_down_sync(0xFFFFFFFFu, v.x, o);
            v.y += __shfl_down_sync(0xFFFFFFFFu, v.y, o);
            v.z += __shfl_down_sync(0xFFFFFFFFu, v.z, o);
            v.w += __shfl_down_sync(0xFFFFFFFFu, v.w, o);
        }
        if (lane == 0)
            ((float4*)g_P)[(h * NP + p) * 32 + wid] = v;
    }
}

// ---------------------------------------------------------------------------
// k_out: fresh full grid, pure stream. 1024 blocks x 256 threads, exactly one
// float4 per thread: out = (P0[i0]+P1[i0]+P0[i1]+P1[i1]) * q.
// q load issued first (independent DRAM) so it overlaps the idx->P chain.
// ---------------------------------------------------------------------------
__global__ void __launch_bounds__(ONTHR) k_out(
    const int*   __restrict__ idx,
    const float* __restrict__ q,
    float*       __restrict__ out)
{
    const int i   = blockIdx.x * ONTHR + threadIdx.x;  // 0 .. 262143
    const int tok = i >> 5;                            // 32 float4 per token
    const int d4  = i & 31;
    const float4 qv = __ldg((const float4*)q + i);     // leads the chain
    const int2   ii = __ldg((const int2*)idx + tok);
    const float4* P0 = (const float4*)g_P;             // half-0 rows
    const float4* P1 = P0 + NP * (Dd / 4);             // half-1 rows
    float4 a0 = P0[ii.x * 32 + d4];
    float4 b0 = P1[ii.x * 32 + d4];
    float4 a1 = P0[ii.y * 32 + d4];
    float4 b1 = P1[ii.y * 32 + d4];
    float4 o;
    o.x = ((a0.x + b0.x) + (a1.x + b1.x)) * qv.x;
    o.y = ((a0.y + b0.y) + (a1.y + b1.y)) * qv.y;
    o.z = ((a0.z + b0.z) + (a1.z + b1.z)) * qv.z;
    o.w = ((a0.w + b0.w) + (a1.w + b1.w)) * qv.w;
    ((float4*)out)[i] = o;
}

extern "C" void kernel_launch(void* const* d_in, const int* in_sizes, int n_in,
                              void* d_out, int out_size)
{
    const int*   idx     = (const int*)  d_in[0];  // [B,S,K] int32
    const float* keys    = (const float*)d_in[1];  // [B,S,K,C] f32
    const float* values  = (const float*)d_in[2];  // [B,S,D]   f32
    const float* queries = (const float*)d_in[3];  // [B,S,D]   f32
    float*       out     = (float*)d_out;          // [B,S,D]   f32

    (void)in_sizes; (void)n_in; (void)out_size;

    k_scatter<<<NBLK, NTHR>>>(idx, keys, values);
    k_out<<<ONBLK, ONTHR>>>(idx, queries, out);
}

// round 15
// speedup vs baseline: 1.0175x; 1.0175x over previous
#include <cuda_runtime.h>
#include <cstdint>

// Fixed problem shapes
static constexpr int NP     = 128;           // partitions
static constexpr int Cc     = 32;            // key channels
static constexpr int Dd     = 128;           // value/query dim
static constexpr int Bb     = 4;
static constexpr int Ss     = 2048;
static constexpr int Kk     = 2;
static constexpr int NPAIRS = Bb * Ss * Kk;  // 16384
static constexpr int NTOK   = Bb * Ss;       // 8192

static constexpr int NTHR   = 1024;
static constexpr int NBLK   = 2 * NP;        // 256 blocks = (partition, half)
static constexpr int HALFN  = NPAIRS / 2;    // 8192 pairs per half
static constexpr int PER    = HALFN / 4 / NTHR;    // 2 int4 per thread
static constexpr int CAP    = 512;           // per-(p,half) capacity (mean 64, sigma 8)

static constexpr int ONTHR  = 256;
static constexpr int ONBLK  = NTOK * Dd / 4 / ONTHR;  // 1024 blocks, 1 f4/thread

// Persistent scratch: per-(half,partition) partial rows. Fully rewritten by
// k_scatter every launch (gather formulation -> no zeroing, no atomics).
__device__ float g_P[2 * NP * Dd];

// ---------------------------------------------------------------------------
// k_scatter: 256 blocks x 1024 threads, 2 CTAs/SM. Block (p,h):
//   Phase 1:   scan half h of idx (2 int4/thread, strided-coalesced),
//              two-level shfl scan -> deterministic compaction (~64 matches).
//   Phase 1.5: w[m] = mean_c keys[j_m,:], 8 threads/row octet-shfl.
//   Phase 2:   float4 gather thread=(slice,d4); transpose + warp-shfl
//              reduce -> g_P[h][p] row; then PDL trigger so the dependent
//              k_out grid can start while remaining blocks drain.
// ---------------------------------------------------------------------------
__global__ void __launch_bounds__(NTHR, 2) k_scatter(
    const int*   __restrict__ idx,
    const float* __restrict__ keys,
    const float* __restrict__ values)
{
    __shared__ int    js[CAP];
    __shared__ float  wls[CAP];
    __shared__ int    wsum[32];
    __shared__ float4 red4[32][33];          // padded transpose buffer

    const int p    = blockIdx.x >> 1;
    const int h    = blockIdx.x & 1;
    const int tid  = threadIdx.x;
    const int lane = tid & 31;
    const int wid  = tid >> 5;

    // ---- Phase 1a: strided-coalesced idx load (2 int4/thread), count
    const int4* idx4 = (const int4*)idx + h * (HALFN / 4);
    int4 my[PER];
    int cnt = 0;
    #pragma unroll
    for (int i = 0; i < PER; i++) {
        my[i] = idx4[i * NTHR + tid];
        cnt += (my[i].x == p) + (my[i].y == p) + (my[i].z == p) + (my[i].w == p);
    }

    // ---- Phase 1b: two-level exclusive scan (warp shfl + 32-entry top)
    int inc = cnt;
    #pragma unroll
    for (int o = 1; o < 32; o <<= 1) {
        int v = __shfl_up_sync(0xFFFFFFFFu, inc, o);
        if (lane >= o) inc += v;
    }
    if (lane == 31) wsum[wid] = inc;
    __syncthreads();
    if (wid == 0) {
        int v = wsum[lane];
        #pragma unroll
        for (int o = 1; o < 32; o <<= 1) {
            int u = __shfl_up_sync(0xFFFFFFFFu, v, o);
            if (lane >= o) v += u;
        }
        wsum[lane] = v;                      // inclusive prefix of warp totals
    }
    __syncthreads();
    int n   = wsum[31];
    int pos = (wid ? wsum[wid - 1] : 0) + (inc - cnt);

    // ---- Phase 1c: emit matched pair indices (fixed deterministic order)
    #pragma unroll
    for (int i = 0; i < PER; i++) {
        const int j = h * HALFN + (i * NTHR + tid) * 4;
        if (my[i].x == p && pos < CAP) js[pos++] = j + 0;
        if (my[i].y == p && pos < CAP) js[pos++] = j + 1;
        if (my[i].z == p && pos < CAP) js[pos++] = j + 2;
        if (my[i].w == p && pos < CAP) js[pos++] = j + 3;
    }
    if (n > CAP) n = CAP;
    __syncthreads();

    // ---- Phase 1.5: weights, 8 threads per 128B key row, octet shfl.
    {
        const int lane8 = tid & 7;
        const int row8  = tid >> 3;
        for (int b = 0; b < n; b += NTHR / 8) {
            const int m = b + row8;
            float s = 0.f;
            if (m < n) {
                float4 v = ((const float4*)keys)[(size_t)js[m] * (Cc / 4) + lane8];
                s = (v.x + v.y) + (v.z + v.w);
            }
            s += __shfl_xor_sync(0xFFFFFFFFu, s, 1);
            s += __shfl_xor_sync(0xFFFFFFFFu, s, 2);
            s += __shfl_xor_sync(0xFFFFFFFFu, s, 4);
            if (m < n && lane8 == 0) wls[m] = s * (1.0f / Cc);
        }
    }
    __syncthreads();

    // ---- Phase 2: float4 gather, thread=(slice,d4); ~2 matches/thread.
    {
        const int slice = tid >> 5;
        const int d4    = tid & 31;
        const float4* V4 = (const float4*)values;
        float4 acc = make_float4(0.f, 0.f, 0.f, 0.f);
        for (int m = slice; m < n; m += 32) {
            const float w = wls[m];
            float4 v = V4[(js[m] >> 1) * 32 + d4];
            acc.x += w * v.x; acc.y += w * v.y;
            acc.z += w * v.z; acc.w += w * v.w;
        }
        red4[slice][d4] = acc;
        __syncthreads();
        // warp-transpose reduce: warp `wid` owns column d4=wid, lanes=slices
        float4 v = red4[lane][wid];
        #pragma unroll
        for (int o = 16; o >= 1; o >>= 1) {
            v.x += __shfl_down_sync(0xFFFFFFFFu, v.x, o);
            v.y += __shfl_down_sync(0xFFFFFFFFu, v.y, o);
            v.z += __shfl_down_sync(0xFFFFFFFFu, v.z, o);
            v.w += __shfl_down_sync(0xFFFFFFFFu, v.w, o);
        }
        if (lane == 0)
            ((float4*)g_P)[(h * NP + p) * 32 + wid] = v;
    }

    // ---- PDL trigger: this block's g_P row is stored; allow the dependent
    // grid (k_out) to begin scheduling. Visibility of the stores above for
    // consumers is established by griddepcontrol.wait in k_out.
    __syncthreads();
    asm volatile("griddepcontrol.launch_dependents;" ::: "memory");
}

// ---------------------------------------------------------------------------
// k_out: PDL-overlapped streamer. 1024 blocks x 256 threads, exactly one
// float4 per thread. The q/idx loads (independent of g_P) issue BEFORE
// griddepcontrol.wait, so they overlap k_scatter's tail; only the P-row
// reads sit behind the dependency.
// ---------------------------------------------------------------------------
__global__ void __launch_bounds__(ONTHR) k_out(
    const int*   __restrict__ idx,
    const float* __restrict__ q,
    float*       __restrict__ out)
{
    const int i   = blockIdx.x * ONTHR + threadIdx.x;  // 0 .. 262143
    const int tok = i >> 5;                            // 32 float4 per token
    const int d4  = i & 31;
    const float4 qv = __ldg((const float4*)q + i);     // pre-dependency loads
    const int2   ii = __ldg((const int2*)idx + tok);

    asm volatile("griddepcontrol.wait;" ::: "memory"); // g_P now visible

    const float4* P0 = (const float4*)g_P;             // half-0 rows
    const float4* P1 = P0 + NP * (Dd / 4);             // half-1 rows
    float4 a0 = P0[ii.x * 32 + d4];
    float4 b0 = P1[ii.x * 32 + d4];
    float4 a1 = P0[ii.y * 32 + d4];
    float4 b1 = P1[ii.y * 32 + d4];
    float4 o;
    o.x = ((a0.x + b0.x) + (a1.x + b1.x)) * qv.x;
    o.y = ((a0.y + b0.y) + (a1.y + b1.y)) * qv.y;
    o.z = ((a0.z + b0.z) + (a1.z + b1.z)) * qv.z;
    o.w = ((a0.w + b0.w) + (a1.w + b1.w)) * qv.w;
    ((float4*)out)[i] = o;
}

extern "C" void kernel_launch(void* const* d_in, const int* in_sizes, int n_in,
                              void* d_out, int out_size)
{
    const int*   idx     = (const int*)  d_in[0];  // [B,S,K] int32
    const float* keys    = (const float*)d_in[1];  // [B,S,K,C] f32
    const float* values  = (const float*)d_in[2];  // [B,S,D]   f32
    const float* queries = (const float*)d_in[3];  // [B,S,D]   f32
    float*       out     = (float*)d_out;          // [B,S,D]   f32

    (void)in_sizes; (void)n_in; (void)out_size;

    k_scatter<<<NBLK, NTHR>>>(idx, keys, values);

    // Dependent launch with programmatic stream serialization: k_out may
    // begin once k_scatter's blocks have triggered launch_dependents.
    cudaLaunchConfig_t cfg = {};
    cfg.gridDim  = dim3(ONBLK, 1, 1);
    cfg.blockDim = dim3(ONTHR, 1, 1);
    cfg.dynamicSmemBytes = 0;
    cfg.stream = 0;
    cudaLaunchAttribute attrs[1];
    attrs[0].id = cudaLaunchAttributeProgrammaticStreamSerialization;
    attrs[0].val.programmaticStreamSerializationAllowed = 1;
    cfg.attrs = attrs;
    cfg.numAttrs = 1;
    cudaLaunchKernelEx(&cfg, k_out, idx, queries, out);
}